// round 15
// baseline (speedup 1.0000x reference)
#include <cuda_runtime.h>
#include <cuda_fp16.h>
#include <cstdint>
#include <cstddef>

#define N_NODES 100000
#define N_EDGES 1600000
#define F_IN    128
#define HID     150
#define K2      160      // layer2 K: 150 padded to 160
#define N1      160      // layer1 out cols: 150 padded to 160
#define N_OUT   128
#define BCAP    64       // bucket capacity per node (max Poisson(16) degree ~45)

// ---------------- scratch (static device globals) ----------------------------
__device__ __align__(16) int g_cnt[N_NODES];                      // degree counts
__device__ __align__(16) int g_bucket[(size_t)N_NODES * BCAP];    // edge buckets
__device__ __align__(16) int g_wq[2];
__device__ __align__(16) __half g_xh[(size_t)N_NODES * F_IN];     // fp16 copy of x
__device__ __align__(16) __half g_agg1h[(size_t)N_NODES * F_IN];  // deginv-scaled, fp16
__device__ __align__(16) __half g_h1[(size_t)N_NODES * K2];       // fp16
__device__ __align__(16) __half g_t2[(size_t)N_NODES * N_OUT];    // fp16
// fragment-order fp16 weights: [chunk][ntile][lane][4 words], hi/lo split
__device__ __align__(16) uint32_t g_Bf1hi[8 * 20 * 128];   // [Ws1;Wn1]: KCH=8, NT=20
__device__ __align__(16) uint32_t g_Bf1lo[8 * 20 * 128];
__device__ __align__(16) uint32_t g_Bf2hi[5 * 32 * 128];   // [Wn2|Ws2]: KCH=5, NT=32
__device__ __align__(16) uint32_t g_Bf2lo[5 * 32 * 128];
__device__ __align__(16) float g_b1p[N1];

// ---------------- helpers ------------------------------------------------------
__device__ __forceinline__ void split_f16(float v, __half& h, __half& l) {
    h = __float2half_rn(v);
    l = __float2half_rn(v - __half2float(h));
}
__device__ __forceinline__ uint32_t packh2(float a, float b) {
    __half2 h = __floats2half2_rn(a, b);
    return *(uint32_t*)&h;
}
__device__ __forceinline__ void mma16816h(float* d, const uint32_t* a, const uint32_t* b) {
    asm volatile(
        "mma.sync.aligned.m16n8k16.row.col.f32.f16.f16.f32 "
        "{%0,%1,%2,%3}, {%4,%5,%6,%7}, {%8,%9}, {%0,%1,%2,%3};"
        : "+f"(d[0]), "+f"(d[1]), "+f"(d[2]), "+f"(d[3])
        : "r"(a[0]), "r"(a[1]), "r"(a[2]), "r"(a[3]), "r"(b[0]), "r"(b[1]));
}
// fp16 element index inside a fragment-order B buffer for element (n, k)
__device__ __forceinline__ size_t fragIdx(int n, int k, int NT_TOT) {
    int c = k >> 5, kk = k & 31, w = kk >> 1, b = kk & 1;
    int ks = w >> 3, wq = w & 7, q = wq & 3, ch = wq >> 2;
    int slot = ks * 2 + ch;
    int nt = n >> 3, g = n & 7;
    int lane = g * 4 + q;
    int wi = ((c * NT_TOT + nt) * 32 + lane) * 4 + slot;
    return (size_t)wi * 2 + b;
}

// ---------------- prep: weights + x->fp16 + zero counters (one kernel) ---------
__global__ void prep_conv(const float* __restrict__ Ws1,
                          const float* __restrict__ Wn1,
                          const float* __restrict__ Ws2,
                          const float* __restrict__ Wn2,
                          const float* __restrict__ b1,
                          const float2* __restrict__ x) {
    int i = blockIdx.x * 256 + threadIdx.x;   // 25000 blocks -> 6.4M threads
    ((__half2*)g_xh)[i] = __float22half2_rn(x[i]);
    if (i < N_NODES / 4) ((int4*)g_cnt)[i] = make_int4(0, 0, 0, 0);
    if (i < 2) g_wq[i] = 0;
    if (i < 40960) {
        {   // W1 (transposed, padded): n = out col, k 0..255 (self|neigh)
            int n = i >> 8, k = i & 255;
            float w = 0.f;
            if (n < HID) w = (k < F_IN) ? Ws1[k * HID + n] : Wn1[(k - F_IN) * HID + n];
            __half h, l;
            split_f16(w, h, l);
            size_t fi = fragIdx(n, k, 20);
            ((__half*)g_Bf1hi)[fi] = h;
            ((__half*)g_Bf1lo)[fi] = l;
        }
        {   // [Wn2 | Ws2] concat: rows 0..127 = Wn2 cols, 128..255 = Ws2 cols
            int n = i / 160, k = i % 160;
            float w = 0.f;
            if (k < HID) w = (n < 128) ? Wn2[k * N_OUT + n] : Ws2[k * N_OUT + (n - 128)];
            __half h, l;
            split_f16(w, h, l);
            size_t fi = fragIdx(n, k, 32);
            ((__half*)g_Bf2hi)[fi] = h;
            ((__half*)g_Bf2lo)[fi] = l;
        }
    }
    if (i < N1) g_b1p[i] = (i < HID) ? b1[i] : 0.f;
}

// ---------------- one-pass bucket fill (replaces hist + scans + CSR fill) ------
__global__ void fill_bucket(const int* __restrict__ src, const int* __restrict__ dst) {
    int e = blockIdx.x * blockDim.x + threadIdx.x;
    if (e < N_EDGES) {
        int d = dst[e];
        int pos = atomicAdd(&g_cnt[d], 1);
        if (pos < BCAP) g_bucket[(size_t)d * BCAP + pos] = src[e];
    }
}

// ---------------- gather: pair-edge (16 lanes/edge, uint4), fp32 accumulate ----
// FUSE=0: aggh[v] = fp16(deginv * sum feat[bucket[v][j]])
// FUSE=1: outp[v] += deginv * sum feat[bucket[v][j]]   (fp32 RMW)
#define ACC8(u) do { float2 _f; \
    _f = __half22float2(*(const __half2*)&(u).x); acc[0] += _f.x; acc[1] += _f.y; \
    _f = __half22float2(*(const __half2*)&(u).y); acc[2] += _f.x; acc[3] += _f.y; \
    _f = __half22float2(*(const __half2*)&(u).z); acc[4] += _f.x; acc[5] += _f.y; \
    _f = __half22float2(*(const __half2*)&(u).w); acc[6] += _f.x; acc[7] += _f.y; } while (0)

template <int FUSE, int QID>
__global__ void __launch_bounds__(256) gather_h(const __half* __restrict__ feat,
                                                __half* __restrict__ aggh,
                                                float* __restrict__ outp) {
    int lane = threadIdx.x & 31;
    int half = lane >> 4;     // which edge of the pair
    int hl = lane & 15;       // 16B segment within the 256B row
    while (true) {
        int base = 0;
        if (lane == 0) base = atomicAdd(&g_wq[QID], 8);
        base = __shfl_sync(0xffffffffu, base, 0);
        if (base >= N_NODES) break;
        int vend = (base + 8 < N_NODES) ? base + 8 : N_NODES;
        for (int v = base; v < vend; v++) {
            int deg = __ldg(&g_cnt[v]);
            if (deg > BCAP) deg = BCAP;
            const int* cols = g_bucket + (size_t)v * BCAP;
            float acc[8];
#pragma unroll
            for (int j = 0; j < 8; j++) acc[j] = 0.f;
            int e = 0;
            // 4 pair-loads = 8 edges in flight
            for (; e + 8 <= deg; e += 8) {
                int ss[4];
#pragma unroll
                for (int p = 0; p < 4; p++) ss[p] = __ldg(&cols[e + 2 * p + half]);
                uint4 uu[4];
#pragma unroll
                for (int p = 0; p < 4; p++)
                    uu[p] = __ldg((const uint4*)(feat + (size_t)ss[p] * 128) + hl);
#pragma unroll
                for (int p = 0; p < 4; p++) ACC8(uu[p]);
            }
            for (; e + 2 <= deg; e += 2) {
                int s = __ldg(&cols[e + half]);
                uint4 u = __ldg((const uint4*)(feat + (size_t)s * 128) + hl);
                ACC8(u);
            }
            if (e < deg) {
                uint4 u = make_uint4(0, 0, 0, 0);
                if (half == 0) {
                    int s = __ldg(&cols[e]);
                    u = __ldg((const uint4*)(feat + (size_t)s * 128) + hl);
                }
                ACC8(u);
            }
            // fold the two half-warps
#pragma unroll
            for (int j = 0; j < 8; j++)
                acc[j] += __shfl_xor_sync(0xffffffffu, acc[j], 16);
            float dv = (deg > 0) ? (1.f / (float)deg) : 0.f;
            if (half == 0) {
                if (FUSE == 0) {
                    uint4 w;
                    w.x = packh2(dv * acc[0], dv * acc[1]);
                    w.y = packh2(dv * acc[2], dv * acc[3]);
                    w.z = packh2(dv * acc[4], dv * acc[5]);
                    w.w = packh2(dv * acc[6], dv * acc[7]);
                    ((uint4*)(aggh + (size_t)v * 128))[hl] = w;
                } else {
                    float* row = outp + (size_t)v * 128 + hl * 8;
                    float4 a = *(float4*)row;
                    float4 b = *(float4*)(row + 4);
                    a.x += dv * acc[0]; a.y += dv * acc[1];
                    a.z += dv * acc[2]; a.w += dv * acc[3];
                    b.x += dv * acc[4]; b.y += dv * acc[5];
                    b.z += dv * acc[6]; b.w += dv * acc[7];
                    *(float4*)row = a;
                    *(float4*)(row + 4) = b;
                }
            }
        }
    }
}

// ---------------- mma.sync 2-pass fp16 GEMM, BM=128, 512 threads ---------------
// C = A16 * (Bhi + Blo); A plain fp16, B split fp16 hi/lo (exact weights).
// 16 warps (4 m x 4 n); each warp 32 rows x BN/4 cols.
// MODE 1: A = [xh | agg1h] fp16 (K=256), h1 = relu(C + b1p) -> fp16, BN=160
// MODE 2: A = h1 fp16 (K=160), B = [Wn2|Ws2] (BN=256):
//         cols<128 -> t2 (fp16) ; cols>=128 -> out = C + b2 (fp32)
template <int MODE>
__global__ void __launch_bounds__(512, 1)
mma_gemm(const __half* __restrict__ Ah, const __half* __restrict__ A2h,
         const uint4* __restrict__ Bhi, const uint4* __restrict__ Blo,
         const float* __restrict__ bias, __half* __restrict__ Ch,
         float* __restrict__ C2) {
    constexpr int BN    = (MODE == 1) ? 160 : 256;
    constexpr int KCH   = (MODE == 1) ? 8 : 5;
    constexpr int NTT   = BN / 8;
    constexpr int NTW   = BN / 32;
    constexpr int CHW   = NTT * 128;
    constexpr int BUFW  = 2048 + 2 * CHW;      // A plane (2048 w) + B hi + B lo
    constexpr int BPASS = (NTT * 32 + 511) / 512;

    extern __shared__ uint32_t sm[];
    int tid = threadIdx.x, wid = tid >> 5, lid = tid & 31;
    int warp_m = wid & 3, warp_n = wid >> 2;
    int g = lid >> 2, q = lid & 3;
    int permlid = lid ^ ((lid >> 3) & 3);
    int row0 = blockIdx.x * 128;

    float acc[2][NTW][4];
#pragma unroll
    for (int mt = 0; mt < 2; mt++)
#pragma unroll
        for (int nt = 0; nt < NTW; nt++)
#pragma unroll
            for (int r = 0; r < 4; r++) acc[mt][nt][r] = 0.f;

    int srow = tid >> 2, sseg = tid & 3;       // 128 rows x 4 segs (8 fp16 each)
    int grow = row0 + srow;
    int t_w = srow >> 4, rr = srow & 15, gw = rr & 7, rowhalf = rr >> 3;

    uint32_t aw[4];
    uint4 bhv[BPASS], blv[BPASS];

    auto ldg_tile = [&](int c) {
#pragma unroll
        for (int j = 0; j < 4; j++) aw[j] = 0u;
        if (grow < N_NODES) {
            const __half* sp;
            if (MODE == 1)
                sp = (c < 4) ? (Ah + (size_t)grow * 128 + c * 32)
                             : (A2h + (size_t)grow * 128 + (c - 4) * 32);
            else
                sp = Ah + (size_t)grow * K2 + c * 32;
            uint4 v = *(const uint4*)(sp + sseg * 8);
            aw[0] = v.x; aw[1] = v.y; aw[2] = v.z; aw[3] = v.w;
        }
#pragma unroll
        for (int p = 0; p < BPASS; p++) {
            int u = tid + p * 512;
            if (u < NTT * 32) {
                bhv[p] = Bhi[c * (NTT * 32) + u];
                blv[p] = Blo[c * (NTT * 32) + u];
            }
        }
    };
    auto sts_tile = [&](int b) {
        uint32_t* base = sm + b * BUFW;
#pragma unroll
        for (int j = 0; j < 4; j++) {
            int w = sseg * 4 + j;
            int ks = w >> 3, wq = w & 7, qf = wq & 3, ch = wq >> 2;
            int slot = rowhalf + 2 * ch;
            int lane = gw * 4 + qf;
            int lp = lane ^ ((lane >> 3) & 3);
            int idx = ((t_w * 2 + ks) * 32 + lp) * 4 + slot;
            base[idx] = aw[j];
        }
        uint4* Bh4 = (uint4*)(base + 2048);
        uint4* Bl4 = (uint4*)(base + 2048 + CHW);
#pragma unroll
        for (int p = 0; p < BPASS; p++) {
            int u = tid + p * 512;
            if (u < NTT * 32) {
                Bh4[u] = bhv[p];
                Bl4[u] = blv[p];
            }
        }
    };

    ldg_tile(0);
    sts_tile(0);
    __syncthreads();

    for (int c = 0; c < KCH; c++) {
        if (c + 1 < KCH) ldg_tile(c + 1);

        uint32_t* base = sm + (c & 1) * BUFW;
        uint4 AH[2][2];   // [mt][ks]
#pragma unroll
        for (int mt = 0; mt < 2; mt++)
#pragma unroll
            for (int ks = 0; ks < 2; ks++) {
                int t = warp_m * 2 + mt;
                int idx = ((t * 2 + ks) * 32 + permlid) * 4;
                AH[mt][ks] = *(const uint4*)(base + idx);
            }
#pragma unroll
        for (int nt = 0; nt < NTW; nt++) {
            int unit = (warp_n * NTW + nt) * 32 + lid;
            uint4 BH = *(const uint4*)(base + 2048 + unit * 4);
            uint4 BL = *(const uint4*)(base + 2048 + CHW + unit * 4);
            const uint32_t* bhw = (const uint32_t*)&BH;
            const uint32_t* blw = (const uint32_t*)&BL;
#pragma unroll
            for (int ks = 0; ks < 2; ks++) {
                uint32_t b2h[2] = {bhw[ks * 2], bhw[ks * 2 + 1]};
                uint32_t b2l[2] = {blw[ks * 2], blw[ks * 2 + 1]};
#pragma unroll
                for (int mt = 0; mt < 2; mt++) {
                    mma16816h(acc[mt][nt], (const uint32_t*)&AH[mt][ks], b2h);
                    mma16816h(acc[mt][nt], (const uint32_t*)&AH[mt][ks], b2l);
                }
            }
        }
        if (c + 1 < KCH) {
            sts_tile((c + 1) & 1);
            __syncthreads();
        }
    }

    // epilogue
#pragma unroll
    for (int mt = 0; mt < 2; mt++) {
        int r0 = row0 + warp_m * 32 + mt * 16 + g;
#pragma unroll
        for (int nt = 0; nt < NTW; nt++) {
            int cb = warp_n * (BN / 4) + nt * 8 + q * 2;
            float v0 = acc[mt][nt][0], v1 = acc[mt][nt][1];
            float v2 = acc[mt][nt][2], v3 = acc[mt][nt][3];
            if (MODE == 1) {
                float b0 = __ldg(&bias[cb]), b1v = __ldg(&bias[cb + 1]);
                v0 = fmaxf(v0 + b0, 0.f); v1 = fmaxf(v1 + b1v, 0.f);
                v2 = fmaxf(v2 + b0, 0.f); v3 = fmaxf(v3 + b1v, 0.f);
                if (r0 < N_NODES)
                    *(__half2*)(Ch + (size_t)r0 * K2 + cb) = __floats2half2_rn(v0, v1);
                if (r0 + 8 < N_NODES)
                    *(__half2*)(Ch + (size_t)(r0 + 8) * K2 + cb) = __floats2half2_rn(v2, v3);
            } else {
                if (cb < 128) {
                    if (r0 < N_NODES)
                        *(__half2*)(Ch + (size_t)r0 * 128 + cb) = __floats2half2_rn(v0, v1);
                    if (r0 + 8 < N_NODES)
                        *(__half2*)(Ch + (size_t)(r0 + 8) * 128 + cb) = __floats2half2_rn(v2, v3);
                } else {
                    int oc = cb - 128;
                    float b0 = __ldg(&bias[oc]), b1v = __ldg(&bias[oc + 1]);
                    v0 += b0; v1 += b1v; v2 += b0; v3 += b1v;
                    if (r0 < N_NODES)     *(float2*)(C2 + (size_t)r0 * 128 + oc) = make_float2(v0, v1);
                    if (r0 + 8 < N_NODES) *(float2*)(C2 + (size_t)(r0 + 8) * 128 + oc) = make_float2(v2, v3);
                }
            }
        }
    }
}

// ---------------- launch --------------------------------------------------------
extern "C" void kernel_launch(void* const* d_in, const int* in_sizes, int n_in,
                              void* d_out, int out_size) {
    const float* x   = (const float*)d_in[0];
    const int*   src = (const int*)d_in[1];
    const int*   dst = (const int*)d_in[2];
    const float* Ws1 = (const float*)d_in[3];
    const float* Wn1 = (const float*)d_in[4];
    const float* b1  = (const float*)d_in[5];
    const float* Ws2 = (const float*)d_in[6];
    const float* Wn2 = (const float*)d_in[7];
    const float* b2  = (const float*)d_in[8];
    float* out = (float*)d_out;

    float* p_b1p;
    __half *p_xh, *p_agg1h, *p_h1, *p_t2;
    uint32_t *p_B1hi, *p_B1lo, *p_B2hi, *p_B2lo;
    cudaGetSymbolAddress((void**)&p_b1p,   g_b1p);
    cudaGetSymbolAddress((void**)&p_xh,    g_xh);
    cudaGetSymbolAddress((void**)&p_agg1h, g_agg1h);
    cudaGetSymbolAddress((void**)&p_h1,    g_h1);
    cudaGetSymbolAddress((void**)&p_t2,    g_t2);
    cudaGetSymbolAddress((void**)&p_B1hi,  g_Bf1hi);
    cudaGetSymbolAddress((void**)&p_B1lo,  g_Bf1lo);
    cudaGetSymbolAddress((void**)&p_B2hi,  g_Bf2hi);
    cudaGetSymbolAddress((void**)&p_B2lo,  g_Bf2lo);

    constexpr int SMEM1 = 2 * (2048 + 2 * 20 * 128) * 4;   // 57344
    constexpr int SMEM2 = 2 * (2048 + 2 * 32 * 128) * 4;   // 81920
    cudaFuncSetAttribute(mma_gemm<1>, cudaFuncAttributeMaxDynamicSharedMemorySize, SMEM1);
    cudaFuncSetAttribute(mma_gemm<2>, cudaFuncAttributeMaxDynamicSharedMemorySize, SMEM2);

    const int MB = (N_NODES + 127) / 128;   // 782

    // prep (weights + x->fp16 + zero cnt/wq), then one-pass bucket fill
    prep_conv<<<25000, 256>>>(Ws1, Wn1, Ws2, Wn2, b1, (const float2*)x);
    fill_bucket<<<N_EDGES / 256, 256>>>(src, dst);

    // layer 1: agg (fp16) then h1 = relu([xh | agg1h] @ W1 + b1) -> fp16
    gather_h<0, 0><<<1184, 256>>>(p_xh, p_agg1h, nullptr);
    mma_gemm<1><<<MB, 512, SMEM1>>>(p_xh, p_agg1h, (const uint4*)p_B1hi, (const uint4*)p_B1lo,
                                    p_b1p, p_h1, nullptr);

    // layer 2 (fused): t2 = h1@Wn2 (fp16) ; out = h1@Ws2 + b2 (fp32)
    mma_gemm<2><<<MB, 512, SMEM2>>>(p_h1, nullptr, (const uint4*)p_B2hi, (const uint4*)p_B2lo,
                                    b2, p_t2, out);

    // out += deginv * gather(t2)
    gather_h<1, 1><<<1184, 256>>>(p_t2, nullptr, out);
}

// round 16
// speedup vs baseline: 1.2625x; 1.2625x over previous
#include <cuda_runtime.h>
#include <cuda_fp16.h>
#include <cstdint>
#include <cstddef>

#define N_NODES 100000
#define N_EDGES 1600000
#define F_IN    128
#define HID     150
#define K2      160      // layer2 K: 150 padded to 160
#define N1      160      // layer1 out cols: 150 padded to 160
#define N_OUT   128
#define NB      391      // ceil(N_NODES/256)

// ---------------- scratch (static device globals) ----------------------------
__device__ __align__(16) int g_cnt[N_NODES];
__device__ __align__(16) int g_excl[N_NODES];
__device__ __align__(16) int g_bsum[512];
__device__ __align__(16) int g_rowptr[N_NODES + 1];
__device__ __align__(16) int g_cur[N_NODES];
__device__ __align__(16) int g_col[N_EDGES];
__device__ __align__(16) int g_wq[2];
__device__ __align__(16) __half g_xh[(size_t)N_NODES * F_IN];     // fp16 copy of x
__device__ __align__(16) __half g_agg1h[(size_t)N_NODES * F_IN];  // deginv-scaled, fp16
__device__ __align__(16) __half g_h1[(size_t)N_NODES * K2];       // fp16
__device__ __align__(16) __half g_t2[(size_t)N_NODES * N_OUT];    // fp16
// fragment-order fp16 weights: [chunk][ntile][lane][4 words]
__device__ __align__(16) uint32_t g_Bf1[8 * 20 * 128];   // [Ws1;Wn1]: KCH=8, NT=20
__device__ __align__(16) uint32_t g_Bf2[5 * 32 * 128];   // [Wn2|Ws2]: KCH=5, NT=32
__device__ __align__(16) float g_b1p[N1];

// ---------------- helpers ------------------------------------------------------
__device__ __forceinline__ uint32_t packh2(float a, float b) {
    __half2 h = __floats2half2_rn(a, b);
    return *(uint32_t*)&h;
}
__device__ __forceinline__ void mma16816h(float* d, const uint32_t* a, const uint32_t* b) {
    asm volatile(
        "mma.sync.aligned.m16n8k16.row.col.f32.f16.f16.f32 "
        "{%0,%1,%2,%3}, {%4,%5,%6,%7}, {%8,%9}, {%0,%1,%2,%3};"
        : "+f"(d[0]), "+f"(d[1]), "+f"(d[2]), "+f"(d[3])
        : "r"(a[0]), "r"(a[1]), "r"(a[2]), "r"(a[3]), "r"(b[0]), "r"(b[1]));
}
// fp16 element index inside a fragment-order B buffer for element (n, k)
__device__ __forceinline__ size_t fragIdx(int n, int k, int NT_TOT) {
    int c = k >> 5, kk = k & 31, w = kk >> 1, b = kk & 1;
    int ks = w >> 3, wq = w & 7, q = wq & 3, ch = wq >> 2;
    int slot = ks * 2 + ch;
    int nt = n >> 3, g = n & 7;
    int lane = g * 4 + q;
    int wi = ((c * NT_TOT + nt) * 32 + lane) * 4 + slot;
    return (size_t)wi * 2 + b;
}

// ---------------- prep: weights + x->fp16 + degree histogram (one kernel) ------
__global__ void prep_conv(const float* __restrict__ Ws1,
                          const float* __restrict__ Wn1,
                          const float* __restrict__ Ws2,
                          const float* __restrict__ Wn2,
                          const float* __restrict__ b1,
                          const float2* __restrict__ x,
                          const int* __restrict__ dst) {
    int i = blockIdx.x * 256 + threadIdx.x;   // 25000 blocks -> 6.4M threads
    ((__half2*)g_xh)[i] = __float22half2_rn(x[i]);
    if (i < N_EDGES) atomicAdd(&g_cnt[dst[i]], 1);
    if (i < 40960) {
        {   // W1 (transposed, padded): n = out col, k 0..255 (self|neigh)
            int n = i >> 8, k = i & 255;
            float w = 0.f;
            if (n < HID) w = (k < F_IN) ? Ws1[k * HID + n] : Wn1[(k - F_IN) * HID + n];
            ((__half*)g_Bf1)[fragIdx(n, k, 20)] = __float2half_rn(w);
        }
        {   // [Wn2 | Ws2] concat: rows 0..127 = Wn2 cols, 128..255 = Ws2 cols
            int n = i / 160, k = i % 160;
            float w = 0.f;
            if (k < HID) w = (n < 128) ? Wn2[k * N_OUT + n] : Ws2[k * N_OUT + (n - 128)];
            ((__half*)g_Bf2)[fragIdx(n, k, 32)] = __float2half_rn(w);
        }
    }
    if (i < N1) g_b1p[i] = (i < HID) ? b1[i] : 0.f;
}

// ---------------- CSR build ----------------------------------------------------
__global__ void scan1_kernel() {
    __shared__ int sh[256];
    int tid = threadIdx.x;
    int i = blockIdx.x * 256 + tid;
    int v = (i < N_NODES) ? g_cnt[i] : 0;
    sh[tid] = v;
    __syncthreads();
#pragma unroll
    for (int off = 1; off < 256; off <<= 1) {
        int t = (tid >= off) ? sh[tid - off] : 0;
        __syncthreads();
        sh[tid] += t;
        __syncthreads();
    }
    if (i < N_NODES) g_excl[i] = sh[tid] - v;
    if (tid == 255) g_bsum[blockIdx.x] = sh[255];
}
// also re-zeroes g_cnt (for next call's histogram) and g_wq (for this call's gathers)
__global__ void scan23_kernel() {
    __shared__ int sh[256];
    int bid = blockIdx.x, tid = threadIdx.x;
    int s = 0;
    for (int t = tid; t < bid; t += 256) s += g_bsum[t];
    sh[tid] = s;
    __syncthreads();
#pragma unroll
    for (int off = 128; off > 0; off >>= 1) {
        if (tid < off) sh[tid] += sh[tid + off];
        __syncthreads();
    }
    int boff = sh[0];
    int i = bid * 256 + tid;
    if (i < N_NODES) {
        int r = g_excl[i] + boff;
        g_rowptr[i] = r;
        g_cur[i] = r;
        g_cnt[i] = 0;
    }
    if (bid == 0 && tid == 0) {
        g_rowptr[N_NODES] = N_EDGES;
        g_wq[0] = 0;
        g_wq[1] = 0;
    }
}
__global__ void fill_kernel(const int* __restrict__ src, const int* __restrict__ dst) {
    int e = blockIdx.x * blockDim.x + threadIdx.x;
    if (e < N_EDGES) {
        int pos = atomicAdd(&g_cur[dst[e]], 1);
        g_col[pos] = src[e];
    }
}

// ---------------- gather: pair-edge (16 lanes/edge, uint4), fp32 accumulate ----
// FUSE=0: aggh[v] = fp16(deginv * sum feat[col[e]])
// FUSE=1: outp[v] += deginv * sum feat[col[e]]   (fp32 RMW)
#define ACC8(u) do { float2 _f; \
    _f = __half22float2(*(const __half2*)&(u).x); acc[0] += _f.x; acc[1] += _f.y; \
    _f = __half22float2(*(const __half2*)&(u).y); acc[2] += _f.x; acc[3] += _f.y; \
    _f = __half22float2(*(const __half2*)&(u).z); acc[4] += _f.x; acc[5] += _f.y; \
    _f = __half22float2(*(const __half2*)&(u).w); acc[6] += _f.x; acc[7] += _f.y; } while (0)

template <int FUSE, int QID>
__global__ void __launch_bounds__(256) gather_h(const __half* __restrict__ feat,
                                                __half* __restrict__ aggh,
                                                float* __restrict__ outp) {
    int lane = threadIdx.x & 31;
    int half = lane >> 4;     // which edge of the pair
    int hl = lane & 15;       // 16B segment within the 256B row
    while (true) {
        int base = 0;
        if (lane == 0) base = atomicAdd(&g_wq[QID], 8);
        base = __shfl_sync(0xffffffffu, base, 0);
        if (base >= N_NODES) break;
        int vend = (base + 8 < N_NODES) ? base + 8 : N_NODES;
        for (int v = base; v < vend; v++) {
            int beg = __ldg(&g_rowptr[v]), end = __ldg(&g_rowptr[v + 1]);
            float acc[8];
#pragma unroll
            for (int j = 0; j < 8; j++) acc[j] = 0.f;
            int e = beg;
            // 4 pair-loads = 8 edges in flight
            for (; e + 8 <= end; e += 8) {
                int ss[4];
#pragma unroll
                for (int p = 0; p < 4; p++) ss[p] = __ldg(&g_col[e + 2 * p + half]);
                uint4 uu[4];
#pragma unroll
                for (int p = 0; p < 4; p++)
                    uu[p] = __ldg((const uint4*)(feat + (size_t)ss[p] * 128) + hl);
#pragma unroll
                for (int p = 0; p < 4; p++) ACC8(uu[p]);
            }
            for (; e + 2 <= end; e += 2) {
                int s = __ldg(&g_col[e + half]);
                uint4 u = __ldg((const uint4*)(feat + (size_t)s * 128) + hl);
                ACC8(u);
            }
            if (e < end) {
                uint4 u = make_uint4(0, 0, 0, 0);
                if (half == 0) {
                    int s = __ldg(&g_col[e]);
                    u = __ldg((const uint4*)(feat + (size_t)s * 128) + hl);
                }
                ACC8(u);
            }
            // fold the two half-warps
#pragma unroll
            for (int j = 0; j < 8; j++)
                acc[j] += __shfl_xor_sync(0xffffffffu, acc[j], 16);
            float dv = (end > beg) ? (1.f / (float)(end - beg)) : 0.f;
            if (half == 0) {
                if (FUSE == 0) {
                    uint4 w;
                    w.x = packh2(dv * acc[0], dv * acc[1]);
                    w.y = packh2(dv * acc[2], dv * acc[3]);
                    w.z = packh2(dv * acc[4], dv * acc[5]);
                    w.w = packh2(dv * acc[6], dv * acc[7]);
                    ((uint4*)(aggh + (size_t)v * 128))[hl] = w;
                } else {
                    float* row = outp + (size_t)v * 128 + hl * 8;
                    float4 a = *(float4*)row;
                    float4 b = *(float4*)(row + 4);
                    a.x += dv * acc[0]; a.y += dv * acc[1];
                    a.z += dv * acc[2]; a.w += dv * acc[3];
                    b.x += dv * acc[4]; b.y += dv * acc[5];
                    b.z += dv * acc[6]; b.w += dv * acc[7];
                    *(float4*)row = a;
                    *(float4*)(row + 4) = b;
                }
            }
        }
    }
}

// ---------------- mma.sync single-pass fp16 GEMM, BM=128, 512 threads ----------
// C = A16 * B16 (both plain fp16). 16 warps (4 m x 4 n); warp: 32 rows x BN/4 cols.
// MODE 1: A = [xh | agg1h] fp16 (K=256), h1 = relu(C + b1p) -> fp16, BN=160
// MODE 2: A = h1 fp16 (K=160), B = [Wn2|Ws2] (BN=256):
//         cols<128 -> t2 (fp16) ; cols>=128 -> out = C + b2 (fp32)
template <int MODE>
__global__ void __launch_bounds__(512, 1)
mma_gemm(const __half* __restrict__ Ah, const __half* __restrict__ A2h,
         const uint4* __restrict__ Bf,
         const float* __restrict__ bias, __half* __restrict__ Ch,
         float* __restrict__ C2) {
    constexpr int BN    = (MODE == 1) ? 160 : 256;
    constexpr int KCH   = (MODE == 1) ? 8 : 5;
    constexpr int NTT   = BN / 8;
    constexpr int NTW   = BN / 32;
    constexpr int CHW   = NTT * 128;
    constexpr int BUFW  = 2048 + CHW;          // A plane (2048 w) + B plane
    constexpr int BPASS = (NTT * 32 + 511) / 512;

    extern __shared__ uint32_t sm[];
    int tid = threadIdx.x, wid = tid >> 5, lid = tid & 31;
    int warp_m = wid & 3, warp_n = wid >> 2;
    int g = lid >> 2, q = lid & 3;
    int permlid = lid ^ ((lid >> 3) & 3);
    int row0 = blockIdx.x * 128;

    float acc[2][NTW][4];
#pragma unroll
    for (int mt = 0; mt < 2; mt++)
#pragma unroll
        for (int nt = 0; nt < NTW; nt++)
#pragma unroll
            for (int r = 0; r < 4; r++) acc[mt][nt][r] = 0.f;

    int srow = tid >> 2, sseg = tid & 3;       // 128 rows x 4 segs (8 fp16 each)
    int grow = row0 + srow;
    int t_w = srow >> 4, rr = srow & 15, gw = rr & 7, rowhalf = rr >> 3;

    uint32_t aw[4];
    uint4 bhv[BPASS];

    auto ldg_tile = [&](int c) {
#pragma unroll
        for (int j = 0; j < 4; j++) aw[j] = 0u;
        if (grow < N_NODES) {
            const __half* sp;
            if (MODE == 1)
                sp = (c < 4) ? (Ah + (size_t)grow * 128 + c * 32)
                             : (A2h + (size_t)grow * 128 + (c - 4) * 32);
            else
                sp = Ah + (size_t)grow * K2 + c * 32;
            uint4 v = *(const uint4*)(sp + sseg * 8);
            aw[0] = v.x; aw[1] = v.y; aw[2] = v.z; aw[3] = v.w;
        }
#pragma unroll
        for (int p = 0; p < BPASS; p++) {
            int u = tid + p * 512;
            if (u < NTT * 32) bhv[p] = Bf[c * (NTT * 32) + u];
        }
    };
    auto sts_tile = [&](int b) {
        uint32_t* base = sm + b * BUFW;
#pragma unroll
        for (int j = 0; j < 4; j++) {
            int w = sseg * 4 + j;
            int ks = w >> 3, wq = w & 7, qf = wq & 3, ch = wq >> 2;
            int slot = rowhalf + 2 * ch;
            int lane = gw * 4 + qf;
            int lp = lane ^ ((lane >> 3) & 3);
            int idx = ((t_w * 2 + ks) * 32 + lp) * 4 + slot;
            base[idx] = aw[j];
        }
        uint4* Bh4 = (uint4*)(base + 2048);
#pragma unroll
        for (int p = 0; p < BPASS; p++) {
            int u = tid + p * 512;
            if (u < NTT * 32) Bh4[u] = bhv[p];
        }
    };

    ldg_tile(0);
    sts_tile(0);
    __syncthreads();

    for (int c = 0; c < KCH; c++) {
        if (c + 1 < KCH) ldg_tile(c + 1);

        uint32_t* base = sm + (c & 1) * BUFW;
        uint4 AH[2][2];   // [mt][ks]
#pragma unroll
        for (int mt = 0; mt < 2; mt++)
#pragma unroll
            for (int ks = 0; ks < 2; ks++) {
                int t = warp_m * 2 + mt;
                int idx = ((t * 2 + ks) * 32 + permlid) * 4;
                AH[mt][ks] = *(const uint4*)(base + idx);
            }
#pragma unroll
        for (int nt = 0; nt < NTW; nt++) {
            int unit = (warp_n * NTW + nt) * 32 + lid;
            uint4 BH = *(const uint4*)(base + 2048 + unit * 4);
            const uint32_t* bhw = (const uint32_t*)&BH;
#pragma unroll
            for (int ks = 0; ks < 2; ks++) {
                uint32_t b2h[2] = {bhw[ks * 2], bhw[ks * 2 + 1]};
#pragma unroll
                for (int mt = 0; mt < 2; mt++)
                    mma16816h(acc[mt][nt], (const uint32_t*)&AH[mt][ks], b2h);
            }
        }
        if (c + 1 < KCH) {
            sts_tile((c + 1) & 1);
            __syncthreads();
        }
    }

    // epilogue
#pragma unroll
    for (int mt = 0; mt < 2; mt++) {
        int r0 = row0 + warp_m * 32 + mt * 16 + g;
#pragma unroll
        for (int nt = 0; nt < NTW; nt++) {
            int cb = warp_n * (BN / 4) + nt * 8 + q * 2;
            float v0 = acc[mt][nt][0], v1 = acc[mt][nt][1];
            float v2 = acc[mt][nt][2], v3 = acc[mt][nt][3];
            if (MODE == 1) {
                float b0 = __ldg(&bias[cb]), b1v = __ldg(&bias[cb + 1]);
                v0 = fmaxf(v0 + b0, 0.f); v1 = fmaxf(v1 + b1v, 0.f);
                v2 = fmaxf(v2 + b0, 0.f); v3 = fmaxf(v3 + b1v, 0.f);
                if (r0 < N_NODES)
                    *(__half2*)(Ch + (size_t)r0 * K2 + cb) = __floats2half2_rn(v0, v1);
                if (r0 + 8 < N_NODES)
                    *(__half2*)(Ch + (size_t)(r0 + 8) * K2 + cb) = __floats2half2_rn(v2, v3);
            } else {
                if (cb < 128) {
                    if (r0 < N_NODES)
                        *(__half2*)(Ch + (size_t)r0 * 128 + cb) = __floats2half2_rn(v0, v1);
                    if (r0 + 8 < N_NODES)
                        *(__half2*)(Ch + (size_t)(r0 + 8) * 128 + cb) = __floats2half2_rn(v2, v3);
                } else {
                    int oc = cb - 128;
                    float b0 = __ldg(&bias[oc]), b1v = __ldg(&bias[oc + 1]);
                    v0 += b0; v1 += b1v; v2 += b0; v3 += b1v;
                    if (r0 < N_NODES)     *(float2*)(C2 + (size_t)r0 * 128 + oc) = make_float2(v0, v1);
                    if (r0 + 8 < N_NODES) *(float2*)(C2 + (size_t)(r0 + 8) * 128 + oc) = make_float2(v2, v3);
                }
            }
        }
    }
}

// ---------------- launch --------------------------------------------------------
extern "C" void kernel_launch(void* const* d_in, const int* in_sizes, int n_in,
                              void* d_out, int out_size) {
    const float* x   = (const float*)d_in[0];
    const int*   src = (const int*)d_in[1];
    const int*   dst = (const int*)d_in[2];
    const float* Ws1 = (const float*)d_in[3];
    const float* Wn1 = (const float*)d_in[4];
    const float* b1  = (const float*)d_in[5];
    const float* Ws2 = (const float*)d_in[6];
    const float* Wn2 = (const float*)d_in[7];
    const float* b2  = (const float*)d_in[8];
    float* out = (float*)d_out;

    float* p_b1p;
    __half *p_xh, *p_agg1h, *p_h1, *p_t2;
    uint32_t *p_B1, *p_B2;
    cudaGetSymbolAddress((void**)&p_b1p,   g_b1p);
    cudaGetSymbolAddress((void**)&p_xh,    g_xh);
    cudaGetSymbolAddress((void**)&p_agg1h, g_agg1h);
    cudaGetSymbolAddress((void**)&p_h1,    g_h1);
    cudaGetSymbolAddress((void**)&p_t2,    g_t2);
    cudaGetSymbolAddress((void**)&p_B1,    g_Bf1);
    cudaGetSymbolAddress((void**)&p_B2,    g_Bf2);

    constexpr int SMEM1 = 2 * (2048 + 20 * 128) * 4;   // 36864
    constexpr int SMEM2 = 2 * (2048 + 32 * 128) * 4;   // 49152
    cudaFuncSetAttribute(mma_gemm<1>, cudaFuncAttributeMaxDynamicSharedMemorySize, SMEM1);
    cudaFuncSetAttribute(mma_gemm<2>, cudaFuncAttributeMaxDynamicSharedMemorySize, SMEM2);

    const int MB = (N_NODES + 127) / 128;   // 782

    // prep (weights + x->fp16 + degree hist; g_cnt zeroed by prior call's scan23,
    // zero-init on call 1), then CSR build (scan23 also resets g_cnt + g_wq)
    prep_conv<<<25000, 256>>>(Ws1, Wn1, Ws2, Wn2, b1, (const float2*)x, dst);
    scan1_kernel<<<NB, 256>>>();
    scan23_kernel<<<NB, 256>>>();
    fill_kernel<<<N_EDGES / 256, 256>>>(src, dst);

    // layer 1: agg (fp16) then h1 = relu([xh | agg1h] @ W1 + b1) -> fp16
    gather_h<0, 0><<<1184, 256>>>(p_xh, p_agg1h, nullptr);
    mma_gemm<1><<<MB, 512, SMEM1>>>(p_xh, p_agg1h, (const uint4*)p_B1,
                                    p_b1p, p_h1, nullptr);

    // layer 2 (fused): t2 = h1@Wn2 (fp16) ; out = h1@Ws2 + b2 (fp32)
    mma_gemm<2><<<MB, 512, SMEM2>>>(p_h1, nullptr, (const uint4*)p_B2,
                                    b2, p_t2, out);

    // out += deginv * gather(t2)
    gather_h<1, 1><<<1184, 256>>>(p_t2, nullptr, out);
}